// round 17
// baseline (speedup 1.0000x reference)
#include <cuda_runtime.h>
#include <cuda_fp16.h>
#include <cstdint>

// ----------------------------------------------------------------------------
// TensorProductWithScalarComponents — mma.sync fp16 HMMA, f16 accumulators
// (Round 16)
//
// R16 = R15 pipeline (cp.async.ca pair staging, fragment-pair uint4 B,
//       fused dispatch) restructured to ONE 512-thread CTA:
//       16 warps = 4 m-groups x 4 n-groups, NTW = NT/4.
//   MMA switched to m16n8k16.f16.f16.f16.f16 (historically 2x the f32-acc
//   rate). f16 accumulation is confined to ONE u-chunk (4 chained mmas,
//   K=64), then promoted into fp32 register accumulators -> bounded error
//   (~6.5e-4 predicted, threshold 1e-3).
//   Register budget: acc32(32) + yv(32) + d16(16) + misc ~= 110 < 128.
// ----------------------------------------------------------------------------

#define NS       100000
#define TN       128      // samples per CTA (4 m-groups x 32)
#define NTHREADS 512
#define XS       130      // padded x-tile stride (halfs)

// Folded weights, fp16; blk0/1 pair-packed, blk2 plain fragment order
__device__ __half g_C0[128 * 64 * 128];  // 2 MB
__device__ __half g_C1[64 * 64 * 64];    // 512 KB
__device__ __half g_C2[32 * 64 * 32];    // 128 KB

__device__ __forceinline__ uint32_t hmul2u(uint32_t a, uint32_t b) {
    __half2 r = __hmul2(*(__half2*)&a, *(__half2*)&b);
    return *(uint32_t*)&r;
}

// f16-accumulator HMMA: D(f16) = A(f16)*B(f16) + D(f16)
__device__ __forceinline__ void mma16816_h(uint32_t* d, uint32_t a0, uint32_t a1,
                                           uint32_t a2, uint32_t a3,
                                           uint32_t b0, uint32_t b1) {
    asm volatile(
        "mma.sync.aligned.m16n8k16.row.col.f16.f16.f16.f16 "
        "{%0,%1},{%2,%3,%4,%5},{%6,%7},{%0,%1};"
        : "+r"(d[0]), "+r"(d[1])
        : "r"(a0), "r"(a1), "r"(a2), "r"(a3), "r"(b0), "r"(b1));
}

__device__ __forceinline__ uint32_t smem_u32(const void* p) {
    uint32_t a;
    asm("{ .reg .u64 t; cvta.to.shared.u64 t, %1; cvt.u32.u64 %0, t; }"
        : "=r"(a) : "l"(p));
    return a;
}

#define CP_ASYNC_CA16(dst_smem, src_gmem) \
    asm volatile("cp.async.ca.shared.global [%0], [%1], 16;" \
                 :: "r"(dst_smem), "l"(src_gmem) : "memory")
#define CP_COMMIT() asm volatile("cp.async.commit_group;" ::: "memory")
#define CP_WAIT0()  asm volatile("cp.async.wait_group 0;" ::: "memory")

// ---------------------------------------------------------------------------
// Stage 1: C[u,v,w2] = (1/(8m)) * sum_w Wt[uv,w]*Wl[w,w2], fp16.
// BLK 0/1: n-tile PAIR-packed uint4 layout. BLK 2: plain fragment layout.
// ---------------------------------------------------------------------------
template <int M, int BLK>
__global__ void precompute_kernel(const float* __restrict__ Wt,
                                  const float* __restrict__ Wl) {
    __half* C = (BLK == 0) ? g_C0 : (BLK == 1) ? g_C1 : g_C2;
    constexpr int NT = M / 8;
    __shared__ float wt[M];
    const int uv = blockIdx.x;
    const float* wtrow = Wt + (size_t)uv * M;
    for (int w = threadIdx.x; w < M; w += blockDim.x) wt[w] = wtrow[w];
    __syncthreads();

    const int w2 = threadIdx.x;
    float acc = 0.f;
#pragma unroll 4
    for (int w = 0; w < M; ++w) acc = fmaf(wt[w], Wl[w * M + w2], acc);
    acc *= (1.0f / (8.0f * (float)M));

    const int u = uv >> 6, v = uv & 63;
    const uint32_t lane = (uint32_t)(w2 & 7) * 4 + ((v & 7) >> 1);
    const uint32_t slot = (uint32_t)(v & 1) + (((v >> 3) & 1) << 1);
    const uint32_t nt   = (uint32_t)(w2 >> 3);
    uint32_t idx;
    if (BLK < 2) {  // pair-packed
        idx = (uint32_t)u * (64u * M) +
              (((uint32_t)(v >> 4) * (NT / 2) + (nt >> 1)) * 32u + lane) * 8u +
              (nt & 1) * 4u + slot;
    } else {        // plain
        idx = (uint32_t)u * (64u * M) +
              (((uint32_t)(v >> 4) * NT + nt) * 32u + lane) * 4u + slot;
    }
    C[idx] = __float2half(acc);
}

// ---------------------------------------------------------------------------
// GEMM body. CTA = 128 samples x M outputs for one mc. 512 threads:
// 16 warps = 4 m-groups (2 m-tiles each) x 4 n-groups (NTW = NT/4 tiles).
// f16 accumulation per u-chunk, promoted to fp32 regs each u.
// ---------------------------------------------------------------------------
template <int M, int D, int BLK, int XOFF>
__device__ __forceinline__ void mma_body(const float* __restrict__ x,
                                         const float* __restrict__ y,
                                         float* __restrict__ out, int mc) {
    constexpr int NT   = M / 8;         // total n-tiles (16/8/4)
    constexpr int NTW  = NT / 4;        // n-tiles per warp (4/2/1)
    constexpr int NTP  = (NTW >= 2) ? NTW / 2 : 1;  // pairs (blk0/1)
    constexpr int U    = M;             // u-chunks
    constexpr int CH   = 64 * M;        // halfs per B chunk
    constexpr int PCH  = 2 * CH;        // halfs per chunk PAIR
    constexpr int CPT  = PCH / 8 / NTHREADS;  // cp.async 16B per thread (4/2/1)

    const __half* Cg = (BLK == 0) ? g_C0 : (BLK == 1) ? g_C1 : g_C2;

    extern __shared__ char smem[];
    __half* sx = (__half*)smem;                 // [M][XS] x tile (fp16)
    __half* Bs = (__half*)(smem + M * XS * 2);  // [2][PCH] B pair double buffer
    const uint32_t sBs = smem_u32(Bs);

    const int tid  = threadIdx.x;
    const int wid  = tid >> 5;
    const int lane = tid & 31;
    const int mg   = wid >> 2;        // m-group 0..3
    const int ng   = wid & 3;         // n-group 0..3
    const int n0   = blockIdx.x * TN;
    int nrem = NS - n0; if (nrem > TN) nrem = TN;

    const int s1 = mg * 32 + (lane >> 2);   // 4 sample rows (2 m-tiles)
    const int s2 = s1 + 8;
    const int s3 = s1 + 16;
    const int s4 = s1 + 24;

    // ---- preload y in A-fragment positions for 4 rows ----
    uint32_t yv[4][8];
#pragma unroll
    for (int i = 0; i < 4; ++i) {
        const int s = s1 + i * 8;
        const bool valid = s < nrem;
        const float* yr = y + (size_t)(n0 + s) * 64;
#pragma unroll
        for (int k = 0; k < 4; ++k) {
            const int v0 = 16 * k + 2 * (lane & 3);
            float2 p = make_float2(0.f, 0.f), q = make_float2(0.f, 0.f);
            if (valid) {
                p = *(const float2*)(yr + v0);
                q = *(const float2*)(yr + v0 + 8);
            }
            __half2 hp = __floats2half2_rn(p.x, p.y);
            __half2 hq = __floats2half2_rn(q.x, q.y);
            yv[i][2 * k]     = *(uint32_t*)&hp;
            yv[i][2 * k + 1] = *(uint32_t*)&hq;
        }
    }

    // ---- x tile -> SMEM fp16, transposed [u][s] ----
    for (int idx = tid; idx < M * TN; idx += NTHREADS) {
        const int u = idx % M;
        const int s = idx / M;
        float v = 0.f;
        if (s < nrem) v = x[(size_t)(n0 + s) * 480 + XOFF + u * D + mc];
        sx[u * XS + s] = __float2half(v);
    }

    float acc[2][NTW][4];
#pragma unroll
    for (int h = 0; h < 2; ++h)
#pragma unroll
        for (int t = 0; t < NTW; ++t)
#pragma unroll
            for (int j = 0; j < 4; ++j) acc[h][t][j] = 0.f;

    // ---- prologue: issue async copy of pair 0 ----
    {
        const char* src = (const char*)Cg;
#pragma unroll
        for (int i = 0; i < CPT; ++i) {
            const int o = (tid + i * NTHREADS) * 16;
            CP_ASYNC_CA16(sBs + o, src + o);
        }
        CP_COMMIT();
    }

    // one k-step of f16-acc mmas into d16
#define DO_K(k)                                                                \
    {                                                                          \
        const uint32_t a0 = hmul2u(yv[0][2 * (k)],     x1p);                   \
        const uint32_t a1 = hmul2u(yv[1][2 * (k)],     x2p);                   \
        const uint32_t a2 = hmul2u(yv[0][2 * (k) + 1], x1p);                   \
        const uint32_t a3 = hmul2u(yv[1][2 * (k) + 1], x2p);                   \
        const uint32_t c0 = hmul2u(yv[2][2 * (k)],     x3p);                   \
        const uint32_t c1 = hmul2u(yv[3][2 * (k)],     x4p);                   \
        const uint32_t c2 = hmul2u(yv[2][2 * (k) + 1], x3p);                   \
        const uint32_t c3 = hmul2u(yv[3][2 * (k) + 1], x4p);                   \
        if constexpr (NTW >= 2) {                                              \
            _Pragma("unroll")                                                  \
            for (int ntp = 0; ntp < NTP; ++ntp) {                              \
                const uint4 b = bp4[((k) * (NT / 2) + ng * NTP + ntp) * 32];   \
                mma16816_h(d16[0][2 * ntp],     a0, a1, a2, a3, b.x, b.y);     \
                mma16816_h(d16[1][2 * ntp],     c0, c1, c2, c3, b.x, b.y);     \
                mma16816_h(d16[0][2 * ntp + 1], a0, a1, a2, a3, b.z, b.w);     \
                mma16816_h(d16[1][2 * ntp + 1], c0, c1, c2, c3, b.z, b.w);     \
            }                                                                  \
        } else {                                                               \
            const uint2 b = bp2[((k) * NT + ng) * 32];                         \
            mma16816_h(d16[0][0], a0, a1, a2, a3, b.x, b.y);                   \
            mma16816_h(d16[1][0], c0, c1, c2, c3, b.x, b.y);                   \
        }                                                                      \
    }

    // ---- main loop over pairs: wait(p) -> sync -> issue(p+1) -> compute ----
    for (int p = 0; p < U / 2; ++p) {
        CP_WAIT0();
        __syncthreads();  // pair p visible; compute of p-1 done -> WAR safe

        if (p + 1 < U / 2) {
            const char* src = (const char*)(Cg + (size_t)(p + 1) * PCH);
            const uint32_t dst = sBs + ((p + 1) & 1) * (PCH * 2);
#pragma unroll
            for (int i = 0; i < CPT; ++i) {
                const int o = (tid + i * NTHREADS) * 16;
                CP_ASYNC_CA16(dst + o, src + o);
            }
            CP_COMMIT();
        }

#pragma unroll
        for (int half = 0; half < 2; ++half) {
            const int u = 2 * p + half;
            __half2 h1 = __half2half2(sx[u * XS + s1]);
            __half2 h2 = __half2half2(sx[u * XS + s2]);
            __half2 h3 = __half2half2(sx[u * XS + s3]);
            __half2 h4 = __half2half2(sx[u * XS + s4]);
            const uint32_t x1p = *(uint32_t*)&h1, x2p = *(uint32_t*)&h2;
            const uint32_t x3p = *(uint32_t*)&h3, x4p = *(uint32_t*)&h4;

            const uint4* bp4 = (const uint4*)(Bs + (p & 1) * PCH + half * CH) + lane;
            const uint2* bp2 = (const uint2*)(Bs + (p & 1) * PCH + half * CH) + lane;
            (void)bp4; (void)bp2;

            // f16 accumulators for this u-chunk (K=64 chain)
            uint32_t d16[2][NTW][2];
#pragma unroll
            for (int h = 0; h < 2; ++h)
#pragma unroll
                for (int t = 0; t < NTW; ++t) { d16[h][t][0] = 0u; d16[h][t][1] = 0u; }

            DO_K(0) DO_K(1) DO_K(2) DO_K(3)

            // promote f16 chunk sums into fp32 accumulators
#pragma unroll
            for (int h = 0; h < 2; ++h)
#pragma unroll
                for (int t = 0; t < NTW; ++t) {
                    float2 f0 = __half22float2(*(__half2*)&d16[h][t][0]);
                    float2 f1 = __half22float2(*(__half2*)&d16[h][t][1]);
                    acc[h][t][0] += f0.x; acc[h][t][1] += f0.y;
                    acc[h][t][2] += f1.x; acc[h][t][3] += f1.y;
                }
        }
    }
#undef DO_K

    // ---- store ----
    const int cc = 2 * (lane & 3);
    const int w2b = ng * NTW * 8;
#pragma unroll
    for (int h = 0; h < 2; ++h) {
        const int ra = s1 + h * 16;
        if (ra < nrem) {
            float* orow = out + (size_t)(n0 + ra) * 480 + XOFF + mc;
#pragma unroll
            for (int nt = 0; nt < NTW; ++nt) {
                const int w2 = w2b + nt * 8 + cc;
                orow[(size_t)w2 * D]       = acc[h][nt][0];
                orow[(size_t)(w2 + 1) * D] = acc[h][nt][1];
            }
        }
        const int rb = ra + 8;
        if (rb < nrem) {
            float* orow = out + (size_t)(n0 + rb) * 480 + XOFF + mc;
#pragma unroll
            for (int nt = 0; nt < NTW; ++nt) {
                const int w2 = w2b + nt * 8 + cc;
                orow[(size_t)w2 * D]       = acc[h][nt][2];
                orow[(size_t)(w2 + 1) * D] = acc[h][nt][3];
            }
        }
    }
}

// Fused dispatcher: y=0 -> block0; y=1..3 -> block1 (mc=y-1); y=4..8 -> block2.
__global__ __launch_bounds__(NTHREADS, 1)
void fused_mma_kernel(const float* __restrict__ x,
                      const float* __restrict__ y,
                      float* __restrict__ out) {
    const int by = blockIdx.y;
    if (by == 0)       mma_body<128, 1, 0, 0>(x, y, out, 0);
    else if (by <= 3)  mma_body<64, 3, 1, 128>(x, y, out, by - 1);
    else               mma_body<32, 5, 2, 320>(x, y, out, by - 4);
}

// ---------------------------------------------------------------------------

extern "C" void kernel_launch(void* const* d_in, const int* in_sizes, int n_in,
                              void* d_out, int out_size) {
    // Bind inputs by element count — robust to any metadata ordering.
    const float *x = 0, *y = 0, *Wt0 = 0, *Wt1 = 0, *Wt2 = 0,
                *Wl0 = 0, *Wl1 = 0, *Wl2 = 0;
    for (int i = 0; i < n_in; ++i) {
        const float* p = (const float*)d_in[i];
        switch (in_sizes[i]) {
            case 48000000: x   = p; break;
            case 6400000:  y   = p; break;
            case 1048576:  Wt0 = p; break;
            case 262144:   Wt1 = p; break;
            case 65536:    Wt2 = p; break;
            case 16384:    Wl0 = p; break;
            case 4096:     Wl1 = p; break;
            case 1024:     Wl2 = p; break;
            default: break;
        }
    }
    float* out = (float*)d_out;

    precompute_kernel<128, 0><<<128 * 64, 128>>>(Wt0, Wl0);
    precompute_kernel<64, 1><<<64 * 64, 64>>>(Wt1, Wl1);
    precompute_kernel<32, 2><<<32 * 64, 32>>>(Wt2, Wl2);

    const int ntiles = (NS + TN - 1) / TN;  // 782

    // block0 path: sx 33280 B + 2 pair-buffers of 32768 B = 98816 B
    constexpr int SMMAX = 128 * XS * 2 + 2 * (2 * 64 * 128) * 2;  // 98816

    cudaFuncSetAttribute(fused_mma_kernel,
                         cudaFuncAttributeMaxDynamicSharedMemorySize, SMMAX);

    fused_mma_kernel<<<dim3(ntiles, 9), NTHREADS, SMMAX>>>(x, y, out);
}